// round 12
// baseline (speedup 1.0000x reference)
#include <cuda_runtime.h>
#include <cuda_fp16.h>
#include <math.h>
#include <stdint.h>

#define Bq    128
#define Mseq  1024
#define Ee    1024
#define Hh    8
#define Dd    128
#define MEMN  40
#define MFULL 1064
#define MIDN  64
#define ALPHA_C 1.3f
#define EPS_C   1e-5f
#define SQRT_D_C    11.313708498984760390f   /* sqrt(128) */
#define SQRT_MEM_C  6.3245553203367586640f   /* sqrt(40)  */

/* ---------------- scratch (static device memory: allowed) ---------------- */
__device__ float  g_q   [Bq * Ee];
__device__ float  g_v1  [Bq * Ee];
__device__ float  g_pool[Bq * Hh * MIDN];
__device__ float  g_logits[Bq * Hh * MFULL];

__device__ __half g_hKey [(size_t)Bq * Mseq * Ee];
__device__ __half g_hV2in[(size_t)Bq * Mseq * Ee];
__device__ __half g_hKout[(size_t)Bq * Mseq * Ee];
__device__ __half g_hV2out[(size_t)Bq * Mseq * Ee];
__device__ __half g_hQin [Bq * Ee];
__device__ __half g_hV1in[Bq * Ee];
__device__ __half g_hWq [Ee * Ee];
__device__ __half g_hWk [Ee * Ee];
__device__ __half g_hWv1[Ee * Ee];
__device__ __half g_hWv2[Ee * Ee];
__device__ __half g_hMemK[MEMN * Ee];
__device__ __half g_hMemV[MEMN * Ee];

/* ======================= helpers =========================== */
__device__ __forceinline__ uint32_t smem_u32(const void* p) {
    uint32_t a;
    asm("{ .reg .u64 t; cvta.to.shared.u64 t, %1; cvt.u32.u64 %0, t; }"
        : "=r"(a) : "l"(p));
    return a;
}
__device__ __forceinline__ void cp16(uint32_t s, const void* g) {
    asm volatile("cp.async.ca.shared.global [%0], [%1], 16;"
                 :: "r"(s), "l"(g) : "memory");
}
#define CP_COMMIT() asm volatile("cp.async.commit_group;" ::: "memory")
#define CP_WAIT(n)  asm volatile("cp.async.wait_group %0;" :: "n"(n) : "memory")

#define LDSM_X4(r, a)                                                        \
    asm volatile("ldmatrix.sync.aligned.m8n8.x4.shared.b16 {%0,%1,%2,%3}, [%4];" \
        : "=r"((r)[0]), "=r"((r)[1]), "=r"((r)[2]), "=r"((r)[3]) : "r"(a))
#define LDSM_X2(r, a)                                                        \
    asm volatile("ldmatrix.sync.aligned.m8n8.x2.shared.b16 {%0,%1}, [%2];"   \
        : "=r"((r)[0]), "=r"((r)[1]) : "r"(a))

#define MMA_F16(d, a, b)                                                     \
    asm volatile("mma.sync.aligned.m16n8k16.row.col.f32.f16.f16.f32 "        \
        "{%0,%1,%2,%3}, {%4,%5,%6,%7}, {%8,%9}, {%0,%1,%2,%3};"              \
        : "+f"((d)[0]), "+f"((d)[1]), "+f"((d)[2]), "+f"((d)[3])             \
        : "r"((a)[0]), "r"((a)[1]), "r"((a)[2]), "r"((a)[3]),                \
          "r"((b)[0]), "r"((b)[1]))

/* ---------------- f32 -> f16 conversion pre-pass ---------------- */
__device__ __forceinline__ void cvt_loop(const float4* __restrict__ in,
                                         uint4* __restrict__ out, int n8)
{
    for (int i = blockIdx.x * blockDim.x + threadIdx.x; i < n8;
         i += gridDim.x * blockDim.x) {
        float4 a = in[2 * i], b = in[2 * i + 1];
        __half2 h0 = __floats2half2_rn(a.x, a.y);
        __half2 h1 = __floats2half2_rn(a.z, a.w);
        __half2 h2 = __floats2half2_rn(b.x, b.y);
        __half2 h3 = __floats2half2_rn(b.z, b.w);
        out[i] = make_uint4(*(uint32_t*)&h0, *(uint32_t*)&h1,
                            *(uint32_t*)&h2, *(uint32_t*)&h3);
    }
}
__global__ void __launch_bounds__(256) cvt_f16_kernel(
    const float4* __restrict__ in, uint4* __restrict__ out, int n8)
{
    cvt_loop(in, out, n8);
}
__global__ void __launch_bounds__(256) cvt_w4_kernel(
    const float4* w0, const float4* w1, const float4* w2, const float4* w3,
    uint4* o0, uint4* o1, uint4* o2, uint4* o3, int n8)
{
    const float4* in; uint4* out;
    switch (blockIdx.y) {
        case 0:  in = w0; out = o0; break;
        case 1:  in = w1; out = o1; break;
        case 2:  in = w2; out = o2; break;
        default: in = w3; out = o3; break;
    }
    cvt_loop(in, out, n8);
}
__global__ void __launch_bounds__(256) cvt_qv_kernel(
    const float4* a0, const float4* a1, uint4* o0, uint4* o1, int n8)
{
    cvt_loop(blockIdx.y ? a1 : a0, blockIdx.y ? o1 : o0, n8);
}
__global__ void __launch_bounds__(256) cvt_mem_kernel(
    const float* __restrict__ mem, __half* __restrict__ mk,
    __half* __restrict__ mv, int n)
{
    for (int i = blockIdx.x * blockDim.x + threadIdx.x; i < n;
         i += gridDim.x * blockDim.x) {
        float m = mem[i];
        mk[i] = __float2half(m * SQRT_D_C);
        mv[i] = __float2half(m * SQRT_MEM_C);
    }
}

/* =========================================================================
 * proj_h: C = groupnorm(celu(A @ W^T + bias)), fp16 mma.sync m16n8k16.
 * CTA tile 128x128, BK=64, 4 warps (2x2) of 64x64 warp tiles, 3-stage
 * cp.async, 2 CTAs/SM. Fragment duplication A x2 / B x2 (was x4/x2).
 * grid = (8, rows/128), 128 threads.
 * ========================================================================= */
#define RSTR    144
#define STAGE_B (256 * RSTR)
#define PROJ_SMEM (3 * STAGE_B)          /* 110592 bytes */

__device__ __forceinline__ void proj_issue(
    uint32_t stage, const __half* __restrict__ hA,
    const __half* __restrict__ hW, size_t rowBase, size_t colBase,
    int ch, int tid)
{
#pragma unroll
    for (int i = 0; i < 8; i++) {        /* A: 128 rows x 8 cp16 */
        int idx = tid + 128 * i;
        int r = idx >> 3, c = idx & 7;
        cp16(stage + r * RSTR + c * 16,
             hA + (rowBase + r) * 1024 + ch * 64 + c * 8);
    }
#pragma unroll
    for (int i = 0; i < 8; i++) {        /* W: 128 rows x 8 cp16 */
        int idx = tid + 128 * i;
        int r = idx >> 3, c = idx & 7;
        cp16(stage + (128 + r) * RSTR + c * 16,
             hW + (colBase + r) * 1024 + ch * 64 + c * 8);
    }
}

template <typename OT>
__global__ void __launch_bounds__(128, 2) proj_h(
    const __half* __restrict__ hA, const __half* __restrict__ hW,
    const float* __restrict__ bias, const float* __restrict__ gamma,
    const float* __restrict__ beta, OT* __restrict__ C)
{
    extern __shared__ char smem[];
    const uint32_t sb = smem_u32(smem);

    const int tid  = threadIdx.x;
    const int lane = tid & 31;
    const int wid  = tid >> 5;           /* 0..3 */
    const int wm   = wid >> 1;           /* 0..1 : 64-row slab */
    const int wn   = wid & 1;            /* 0..1 : 64-col slab */
    const int g    = lane >> 2;
    const int tc   = lane & 3;

    const size_t rowBase = (size_t)blockIdx.y * 128;
    const size_t colBase = (size_t)blockIdx.x * 128;

    float acc[4][8][4];
#pragma unroll
    for (int mt = 0; mt < 4; mt++)
#pragma unroll
        for (int nt = 0; nt < 8; nt++)
#pragma unroll
            for (int z = 0; z < 4; z++) acc[mt][nt][z] = 0.f;

    proj_issue(sb + 0 * STAGE_B, hA, hW, rowBase, colBase, 0, tid); CP_COMMIT();
    proj_issue(sb + 1 * STAGE_B, hA, hW, rowBase, colBase, 1, tid); CP_COMMIT();

    const uint32_t aAddrBase =
        (uint32_t)((wm * 64 + (lane & 15)) * RSTR + (lane >> 4) * 16);
    /* B x4: lanes 0-15 -> nt pair lo, 16-31 -> nt pair hi */
    const uint32_t bAddrBase =
        (uint32_t)((128 + wn * 64 + ((lane >> 4) & 1) * 8 + (lane & 7)) * RSTR
                   + ((lane >> 3) & 1) * 16);

    int slot = 0;
    for (int ch = 0; ch < 16; ch++) {
        CP_WAIT(1);
        __syncthreads();
        if (ch + 2 < 16) {
            int ns = slot + 2; if (ns >= 3) ns -= 3;
            proj_issue(sb + ns * STAGE_B, hA, hW, rowBase, colBase, ch + 2, tid);
        }
        CP_COMMIT();

        const uint32_t S = sb + slot * STAGE_B;
        if (++slot == 3) slot = 0;
#pragma unroll
        for (int ks = 0; ks < 4; ks++) {
            uint32_t af[4][4], bf[8][2];
#pragma unroll
            for (int mt = 0; mt < 4; mt++)
                LDSM_X4(af[mt], S + aAddrBase + mt * 16 * RSTR + ks * 32);
#pragma unroll
            for (int j = 0; j < 4; j++) {
                uint32_t t[4];
                LDSM_X4(t, S + bAddrBase + j * 16 * RSTR + ks * 32);
                bf[2 * j][0] = t[0]; bf[2 * j][1] = t[1];
                bf[2 * j + 1][0] = t[2]; bf[2 * j + 1][1] = t[3];
            }
#pragma unroll
            for (int mt = 0; mt < 4; mt++)
#pragma unroll
                for (int nt = 0; nt < 8; nt++)
                    MMA_F16(acc[mt][nt], af[mt], bf[nt]);
        }
    }
    CP_WAIT(0);
    __syncthreads();

    /* ------- epilogue: bias + celu + groupnorm (overlay stage-0 smem) ---- */
    float* SB = (float*)smem;            /* 128 f32 */
    float* SG = SB + 128;
    float* SE = SG + 128;
    float* RS = SE + 128;                /* [128][2] */
    float* RQ = RS + 256;                /* [128][2] */

    SB[tid] = bias [colBase + tid];
    SG[tid] = gamma[colBase + tid];
    SE[tid] = beta [colBase + tid];
    __syncthreads();

#pragma unroll
    for (int mt = 0; mt < 4; mt++)
#pragma unroll
        for (int half = 0; half < 2; half++) {
            const int r = wm * 64 + mt * 16 + half * 8 + g;
            float s = 0.f, q = 0.f;
#pragma unroll
            for (int nt = 0; nt < 8; nt++) {
                const int c0 = wn * 64 + nt * 8 + 2 * tc;
                float x0 = acc[mt][nt][half * 2 + 0] + SB[c0];
                float x1 = acc[mt][nt][half * 2 + 1] + SB[c0 + 1];
                x0 = (x0 > 0.f) ? x0 : ALPHA_C * expm1f(x0 * (1.0f / ALPHA_C));
                x1 = (x1 > 0.f) ? x1 : ALPHA_C * expm1f(x1 * (1.0f / ALPHA_C));
                acc[mt][nt][half * 2 + 0] = x0;
                acc[mt][nt][half * 2 + 1] = x1;
                s += x0 + x1; q += x0 * x0 + x1 * x1;
            }
            s += __shfl_xor_sync(0xffffffffu, s, 1);
            s += __shfl_xor_sync(0xffffffffu, s, 2);
            q += __shfl_xor_sync(0xffffffffu, q, 1);
            q += __shfl_xor_sync(0xffffffffu, q, 2);
            if (tc == 0) { RS[r * 2 + wn] = s; RQ[r * 2 + wn] = q; }
        }
    __syncthreads();

#pragma unroll
    for (int mt = 0; mt < 4; mt++)
#pragma unroll
        for (int half = 0; half < 2; half++) {
            const int r = wm * 64 + mt * 16 + half * 8 + g;
            const float S = RS[r * 2 + 0] + RS[r * 2 + 1];
            const float Q = RQ[r * 2 + 0] + RQ[r * 2 + 1];
            const float mean = S * (1.f / 128.f);
            const float var  = Q * (1.f / 128.f) - mean * mean;
            const float inv  = rsqrtf(var + EPS_C);
            OT* Crow = C + (rowBase + r) * 1024 + colBase;
#pragma unroll
            for (int nt = 0; nt < 8; nt++) {
                const int c0 = wn * 64 + nt * 8 + 2 * tc;
                float ox = (acc[mt][nt][half * 2 + 0] - mean) * inv * SG[c0]     + SE[c0];
                float oy = (acc[mt][nt][half * 2 + 1] - mean) * inv * SG[c0 + 1] + SE[c0 + 1];
                if constexpr (sizeof(OT) == 4) {
                    *(float2*)&Crow[c0] = make_float2(ox, oy);
                } else {
                    *(__half2*)&Crow[c0] = __floats2half2_rn(ox, oy);
                }
            }
        }
}

/* =========================================================================
 * attn_mma: per (b,h) block; q folded into Wb; fp16 mma.sync scoring.
 * ========================================================================= */
#define ASTR      272
#define KSTAGE_B  (128 * ASTR)
#define ATTN_SMEM (64 * ASTR + 3 * KSTAGE_B + 8 * 64 * 4 + 16)

__device__ __forceinline__ void attn_issue(uint32_t stage, int mbase,
                                           int b, int h, int tid)
{
#pragma unroll
    for (int i = 0; i < 8; i++) {
        int c = tid + 256 * i;
        int r = c >> 4, col = c & 15;
        int mg = mbase + r;
        const __half* src;
        if (mg < Mseq) {
            src = g_hKout + ((size_t)(b * Mseq + mg)) * 1024 + h * 128 + col * 8;
        } else {
            int mm = mg - Mseq;
            if (mm >= MEMN) mm = 0;
            src = g_hMemK + (size_t)mm * 1024 + h * 128 + col * 8;
        }
        cp16(stage + r * ASTR + col * 16, src);
    }
}

__global__ void __launch_bounds__(256, 1) attn_mma(
    const float* __restrict__ mask, const float* __restrict__ Wb,
    const float* __restrict__ bb, const float* __restrict__ Wl,
    const float* __restrict__ bl)
{
    extern __shared__ char sm[];
    const uint32_t sb = smem_u32(sm);
    const uint32_t WQ = sb;
    const uint32_t KT = sb + 64 * ASTR;
    float* PR  = (float*)(sm + 64 * ASTR + 3 * KSTAGE_B);
    float* MSM = PR + 8 * 64;

    const int bh = blockIdx.x, b = bh >> 3, h = bh & 7;
    const int tid = threadIdx.x;
    const int lane = tid & 31;
    const int wid  = tid >> 5;
    const int g    = lane >> 2;
    const int tc   = lane & 3;

    const float* qrow = g_q + (size_t)b * 1024 + h * 128;
    for (int idx = tid; idx < 8192; idx += 256) {
        int o = idx >> 7, d = idx & 127;
        float w = Wb[o * 128 + d] * qrow[d];
        *(__half*)(sm + o * ASTR + d * 2) = __float2half(w);
    }
    if (tid < 32) {
        float s = 0.f;
        for (int m = tid; m < MFULL; m += 32) {
            int mm = (m < Mseq) ? m : (m - Mseq);
            s += mask[b * Mseq + mm];
        }
#pragma unroll
        for (int o = 16; o; o >>= 1) s += __shfl_xor_sync(0xffffffffu, s, o);
        if (tid == 0) MSM[0] = s;
    }

    attn_issue(KT + 0 * KSTAGE_B,   0, b, h, tid); CP_COMMIT();
    attn_issue(KT + 1 * KSTAGE_B, 128, b, h, tid); CP_COMMIT();

    float bbf[8][2], wlf[8][2];
#pragma unroll
    for (int nt = 0; nt < 8; nt++) {
        const int c0 = nt * 8 + 2 * tc;
        bbf[nt][0] = bb[c0]; bbf[nt][1] = bb[c0 + 1];
        wlf[nt][0] = Wl[c0]; wlf[nt][1] = Wl[c0 + 1];
    }
    const float bl0 = bl[0];
    const float* maskb = mask + (size_t)b * Mseq;

    float pool[8][2];
#pragma unroll
    for (int nt = 0; nt < 8; nt++) { pool[nt][0] = 0.f; pool[nt][1] = 0.f; }

    const uint32_t aBase = (uint32_t)((wid * 16 + (lane & 15)) * ASTR + (lane >> 4) * 16);
    const uint32_t bBase = (uint32_t)((((lane >> 4) & 1) * 8 + (lane & 7)) * ASTR
                                      + ((lane >> 3) & 1) * 16);

    for (int it = 0; it < 9; it++) {
        CP_WAIT(1);
        __syncthreads();
        if (it + 2 < 9) {
            attn_issue(KT + ((it + 2) % 3) * KSTAGE_B, (it + 2) * 128, b, h, tid);
            CP_COMMIT();
        }
        const uint32_t S = KT + (it % 3) * KSTAGE_B;

        float acc[8][4];
#pragma unroll
        for (int nt = 0; nt < 8; nt++)
#pragma unroll
            for (int z = 0; z < 4; z++) acc[nt][z] = 0.f;

#pragma unroll
        for (int ks = 0; ks < 8; ks++) {
            uint32_t af[4];
            LDSM_X4(af, S + aBase + ks * 32);
#pragma unroll
            for (int j = 0; j < 4; j++) {
                uint32_t t[4];
                LDSM_X4(t, WQ + bBase + j * 16 * ASTR + ks * 32);
                uint32_t b0[2], b1[2];
                b0[0] = t[0]; b0[1] = t[1];
                b1[0] = t[2]; b1[1] = t[3];
                MMA_F16(acc[2 * j],     af, b0);
                MMA_F16(acc[2 * j + 1], af, b1);
            }
        }

        const int mg0 = it * 128 + wid * 16 + g;
        const int mg1 = mg0 + 8;
        float mv0 = 0.f, mv1 = 0.f;
        if (mg0 < MFULL) mv0 = maskb[(mg0 < Mseq) ? mg0 : (mg0 - Mseq)];
        if (mg1 < MFULL) mv1 = maskb[(mg1 < Mseq) ? mg1 : (mg1 - Mseq)];

        float s0 = 0.f, s1 = 0.f;
#pragma unroll
        for (int nt = 0; nt < 8; nt++) {
            float h00 = fmaxf(acc[nt][0] + bbf[nt][0], 0.f);
            float h01 = fmaxf(acc[nt][1] + bbf[nt][1], 0.f);
            float h10 = fmaxf(acc[nt][2] + bbf[nt][0], 0.f);
            float h11 = fmaxf(acc[nt][3] + bbf[nt][1], 0.f);
            s0 += h00 * wlf[nt][0] + h01 * wlf[nt][1];
            s1 += h10 * wlf[nt][0] + h11 * wlf[nt][1];
            pool[nt][0] += h00 * mv0 + h10 * mv1;
            pool[nt][1] += h01 * mv0 + h11 * mv1;
        }
        s0 += __shfl_xor_sync(0xffffffffu, s0, 1);
        s0 += __shfl_xor_sync(0xffffffffu, s0, 2);
        s1 += __shfl_xor_sync(0xffffffffu, s1, 1);
        s1 += __shfl_xor_sync(0xffffffffu, s1, 2);
        if (tc == 0) {
            if (mg0 < MFULL)
                g_logits[(size_t)bh * MFULL + mg0] = (mv0 == 0.f) ? -1e9f : s0 + bl0;
            if (mg1 < MFULL)
                g_logits[(size_t)bh * MFULL + mg1] = (mv1 == 0.f) ? -1e9f : s1 + bl0;
        }
    }

#pragma unroll
    for (int nt = 0; nt < 8; nt++)
#pragma unroll
        for (int c = 0; c < 2; c++) {
            float v = pool[nt][c];
            v += __shfl_xor_sync(0xffffffffu, v, 4);
            v += __shfl_xor_sync(0xffffffffu, v, 8);
            v += __shfl_xor_sync(0xffffffffu, v, 16);
            if (lane < 4) PR[wid * 64 + nt * 8 + 2 * lane + c] = v;
        }
    __syncthreads();
    if (tid < 64) {
        float s = 0.f;
#pragma unroll
        for (int w = 0; w < 8; w++) s += PR[w * 64 + tid];
        g_pool[(size_t)bh * 64 + tid] = s / MSM[0];
    }
}

/* =========================================================================
 * finalize: softmax(logits), channel gate, weighted sum, output
 * ========================================================================= */
__global__ void __launch_bounds__(256) finalize_kernel(
    const float* __restrict__ Wl2, const float* __restrict__ bl2,
    float* __restrict__ out)
{
    __shared__ float alpha[MFULL];
    __shared__ float red[256];
    __shared__ float pool_s[64];
    __shared__ float vpart[256];

    const int bh = blockIdx.x, b = bh >> 3, h = bh & 7;
    const int tid = threadIdx.x;

    float mx = -INFINITY;
    for (int m = tid; m < MFULL; m += 256) {
        float l = g_logits[(size_t)bh * MFULL + m];
        alpha[m] = l;
        mx = fmaxf(mx, l);
    }
    red[tid] = mx;
    __syncthreads();
    for (int s = 128; s > 0; s >>= 1) {
        if (tid < s) red[tid] = fmaxf(red[tid], red[tid + s]);
        __syncthreads();
    }
    mx = red[0];
    __syncthreads();

    float es = 0.f;
    for (int m = tid; m < MFULL; m += 256) {
        float e = expf(alpha[m] - mx);
        alpha[m] = e;
        es += e;
    }
    red[tid] = es;
    if (tid < 64) pool_s[tid] = g_pool[(size_t)bh * 64 + tid];
    __syncthreads();
    for (int s = 128; s > 0; s >>= 1) {
        if (tid < s) red[tid] += red[tid + s];
        __syncthreads();
    }
    const float sumExp = red[0];

    const int d = tid & 127, half = tid >> 7;
    float acc = 0.f;
    for (int m = half; m < MFULL; m += 2) {
        float a = alpha[m];
        float v;
        if (m < Mseq)
            v = __half2float(g_hV2out[((size_t)(b * Mseq + m)) * 1024 + h * 128 + d]);
        else
            v = __half2float(g_hMemV[(size_t)(m - Mseq) * 1024 + h * 128 + d]);
        acc += a * v;
    }
    vpart[tid] = acc;
    __syncthreads();

    if (tid < 128) {
        float v2p = (vpart[tid] + vpart[tid + 128]) / sumExp;
        float s = bl2[d];
#pragma unroll
        for (int o = 0; o < 64; o++) s += pool_s[o] * Wl2[d * 64 + o];
        float ac = 1.f / (1.f + expf(-s));
        size_t oidx = (size_t)b * Ee + h * Dd + d;
        out[oidx] = g_v1[oidx] * v2p * ac;
    }
}

/* ========================================================================= */
extern "C" void kernel_launch(void* const* d_in, const int* in_sizes, int n_in,
                              void* d_out, int out_size)
{
    const float* query  = (const float*)d_in[0];
    const float* key    = (const float*)d_in[1];
    const float* mask   = (const float*)d_in[2];
    const float* value1 = (const float*)d_in[3];
    const float* value2 = (const float*)d_in[4];
    const float* Wq  = (const float*)d_in[5];  const float* bq  = (const float*)d_in[6];
    const float* gq  = (const float*)d_in[7];  const float* sq  = (const float*)d_in[8];
    const float* Wk  = (const float*)d_in[9];  const float* bk  = (const float*)d_in[10];
    const float* gk  = (const float*)d_in[11]; const float* sk  = (const float*)d_in[12];
    const float* Wv1 = (const float*)d_in[13]; const float* bv1 = (const float*)d_in[14];
    const float* gv1 = (const float*)d_in[15]; const float* sv1 = (const float*)d_in[16];
    const float* Wv2 = (const float*)d_in[17]; const float* bv2 = (const float*)d_in[18];
    const float* gv2 = (const float*)d_in[19]; const float* sv2 = (const float*)d_in[20];
    const float* mem = (const float*)d_in[21];
    const float* Wb  = (const float*)d_in[22]; const float* bb  = (const float*)d_in[23];
    const float* Wl  = (const float*)d_in[24]; const float* bl  = (const float*)d_in[25];
    const float* Wl2 = (const float*)d_in[26]; const float* bl2 = (const float*)d_in[27];
    float* out = (float*)d_out;

    void *pq, *pv1;
    cudaGetSymbolAddress(&pq,  g_q);
    cudaGetSymbolAddress(&pv1, g_v1);
    void *phKey, *phV2in, *phKout, *phV2out, *phQ, *phV1;
    void *phWq, *phWk, *phWv1, *phWv2, *phMemK, *phMemV;
    cudaGetSymbolAddress(&phKey,  g_hKey);
    cudaGetSymbolAddress(&phV2in, g_hV2in);
    cudaGetSymbolAddress(&phKout, g_hKout);
    cudaGetSymbolAddress(&phV2out,g_hV2out);
    cudaGetSymbolAddress(&phQ,    g_hQin);
    cudaGetSymbolAddress(&phV1,   g_hV1in);
    cudaGetSymbolAddress(&phWq,   g_hWq);
    cudaGetSymbolAddress(&phWk,   g_hWk);
    cudaGetSymbolAddress(&phWv1,  g_hWv1);
    cudaGetSymbolAddress(&phWv2,  g_hWv2);
    cudaGetSymbolAddress(&phMemK, g_hMemK);
    cudaGetSymbolAddress(&phMemV, g_hMemV);

    cudaFuncSetAttribute(proj_h<float>,
                         cudaFuncAttributeMaxDynamicSharedMemorySize, PROJ_SMEM);
    cudaFuncSetAttribute(proj_h<__half>,
                         cudaFuncAttributeMaxDynamicSharedMemorySize, PROJ_SMEM);
    cudaFuncSetAttribute(attn_mma,
                         cudaFuncAttributeMaxDynamicSharedMemorySize, ATTN_SMEM);

    static cudaStream_t s1 = nullptr;
    static cudaEvent_t eFork, eW, eV2, eQ, eV1;
    if (!s1) {
        cudaStreamCreateWithFlags(&s1, cudaStreamNonBlocking);
        cudaEventCreateWithFlags(&eFork, cudaEventDisableTiming);
        cudaEventCreateWithFlags(&eW,    cudaEventDisableTiming);
        cudaEventCreateWithFlags(&eV2,   cudaEventDisableTiming);
        cudaEventCreateWithFlags(&eQ,    cudaEventDisableTiming);
        cudaEventCreateWithFlags(&eV1,   cudaEventDisableTiming);
    }

    const int BIGN8 = (int)(((size_t)Bq * Mseq * Ee) / 8);

    cudaEventRecord(eFork, 0);
    cudaStreamWaitEvent(s1, eFork, 0);

    /* ---- side stream: weights, value2, q/v1, mem, small projections ---- */
    cvt_w4_kernel<<<dim3(512, 4), 256, 0, s1>>>(
        (const float4*)Wq, (const float4*)Wk, (const float4*)Wv1, (const float4*)Wv2,
        (uint4*)phWq, (uint4*)phWk, (uint4*)phWv1, (uint4*)phWv2, Ee * Ee / 8);
    cudaEventRecord(eW, s1);
    cvt_f16_kernel<<<4096, 256, 0, s1>>>((const float4*)value2,
                                         (uint4*)phV2in, BIGN8);
    cudaEventRecord(eV2, s1);
    cvt_qv_kernel<<<dim3(128, 2), 256, 0, s1>>>(
        (const float4*)query, (const float4*)value1,
        (uint4*)phQ, (uint4*)phV1, Bq * Ee / 8);
    cvt_mem_kernel<<<40, 256, 0, s1>>>(mem, (__half*)phMemK, (__half*)phMemV,
                                       MEMN * Ee);
    proj_h<float><<<dim3(8, 1), 128, PROJ_SMEM, s1>>>(
        (const __half*)phQ,  (const __half*)phWq,  bq,  gq,  sq,  (float*)pq);
    cudaEventRecord(eQ, s1);
    proj_h<float><<<dim3(8, 1), 128, PROJ_SMEM, s1>>>(
        (const __half*)phV1, (const __half*)phWv1, bv1, gv1, sv1, (float*)pv1);
    cudaEventRecord(eV1, s1);

    /* ---- main stream: key cvt, big projections, attention, finalize ---- */
    cvt_f16_kernel<<<4096, 256>>>((const float4*)key, (uint4*)phKey, BIGN8);
    cudaStreamWaitEvent(0, eW, 0);
    proj_h<__half><<<dim3(8, 1024), 128, PROJ_SMEM>>>(
        (const __half*)phKey, (const __half*)phWk, bk, gk, sk, (__half*)phKout);
    cudaStreamWaitEvent(0, eV2, 0);
    proj_h<__half><<<dim3(8, 1024), 128, PROJ_SMEM>>>(
        (const __half*)phV2in, (const __half*)phWv2, bv2, gv2, sv2,
        (__half*)phV2out);
    cudaStreamWaitEvent(0, eQ, 0);
    attn_mma<<<Bq * Hh, 256, ATTN_SMEM>>>(mask, Wb, bb, Wl, bl);
    cudaStreamWaitEvent(0, eV1, 0);
    finalize_kernel<<<Bq * Hh, 256>>>(Wl2, bl2, out);
}

// round 13
// speedup vs baseline: 1.0564x; 1.0564x over previous
#include <cuda_runtime.h>
#include <cuda_fp16.h>
#include <math.h>
#include <stdint.h>

#define Bq    128
#define Mseq  1024
#define Ee    1024
#define Hh    8
#define Dd    128
#define MEMN  40
#define MFULL 1064
#define MIDN  64
#define ALPHA_C 1.3f
#define EPS_C   1e-5f
#define SQRT_D_C    11.313708498984760390f   /* sqrt(128) */
#define SQRT_MEM_C  6.3245553203367586640f   /* sqrt(40)  */

/* ---------------- scratch (static device memory: allowed) ---------------- */
__device__ float  g_q   [Bq * Ee];
__device__ float  g_v1  [Bq * Ee];
__device__ float  g_pool[Bq * Hh * MIDN];
__device__ float  g_logits[Bq * Hh * MFULL];

__device__ __half g_hKey [(size_t)Bq * Mseq * Ee];
__device__ __half g_hV2in[(size_t)Bq * Mseq * Ee];
__device__ __half g_hKout[(size_t)Bq * Mseq * Ee];
__device__ __half g_hV2out[(size_t)Bq * Mseq * Ee];
__device__ __half g_hQin [Bq * Ee];
__device__ __half g_hV1in[Bq * Ee];
__device__ __half g_hWq [Ee * Ee];
__device__ __half g_hWk [Ee * Ee];
__device__ __half g_hWv1[Ee * Ee];
__device__ __half g_hWv2[Ee * Ee];
__device__ __half g_hMemK[MEMN * Ee];
__device__ __half g_hMemV[MEMN * Ee];

/* ======================= helpers =========================== */
__device__ __forceinline__ uint32_t smem_u32(const void* p) {
    uint32_t a;
    asm("{ .reg .u64 t; cvta.to.shared.u64 t, %1; cvt.u32.u64 %0, t; }"
        : "=r"(a) : "l"(p));
    return a;
}
__device__ __forceinline__ void cp16(uint32_t s, const void* g) {
    asm volatile("cp.async.ca.shared.global [%0], [%1], 16;"
                 :: "r"(s), "l"(g) : "memory");
}
#define CP_COMMIT() asm volatile("cp.async.commit_group;" ::: "memory")
#define CP_WAIT(n)  asm volatile("cp.async.wait_group %0;" :: "n"(n) : "memory")

#define LDSM_X4(r, a)                                                        \
    asm volatile("ldmatrix.sync.aligned.m8n8.x4.shared.b16 {%0,%1,%2,%3}, [%4];" \
        : "=r"((r)[0]), "=r"((r)[1]), "=r"((r)[2]), "=r"((r)[3]) : "r"(a))
#define LDSM_X2(r, a)                                                        \
    asm volatile("ldmatrix.sync.aligned.m8n8.x2.shared.b16 {%0,%1}, [%2];"   \
        : "=r"((r)[0]), "=r"((r)[1]) : "r"(a))

#define MMA_F16(d, a, b)                                                     \
    asm volatile("mma.sync.aligned.m16n8k16.row.col.f32.f16.f16.f32 "        \
        "{%0,%1,%2,%3}, {%4,%5,%6,%7}, {%8,%9}, {%0,%1,%2,%3};"              \
        : "+f"((d)[0]), "+f"((d)[1]), "+f"((d)[2]), "+f"((d)[3])             \
        : "r"((a)[0]), "r"((a)[1]), "r"((a)[2]), "r"((a)[3]),                \
          "r"((b)[0]), "r"((b)[1]))

/* ---------------- f32 -> f16 conversion pre-pass ---------------- */
__device__ __forceinline__ void cvt_loop(const float4* __restrict__ in,
                                         uint4* __restrict__ out, int n8)
{
    for (int i = blockIdx.x * blockDim.x + threadIdx.x; i < n8;
         i += gridDim.x * blockDim.x) {
        float4 a = in[2 * i], b = in[2 * i + 1];
        __half2 h0 = __floats2half2_rn(a.x, a.y);
        __half2 h1 = __floats2half2_rn(a.z, a.w);
        __half2 h2 = __floats2half2_rn(b.x, b.y);
        __half2 h3 = __floats2half2_rn(b.z, b.w);
        out[i] = make_uint4(*(uint32_t*)&h0, *(uint32_t*)&h1,
                            *(uint32_t*)&h2, *(uint32_t*)&h3);
    }
}
__global__ void __launch_bounds__(256) cvt_f16_kernel(
    const float4* __restrict__ in, uint4* __restrict__ out, int n8)
{
    cvt_loop(in, out, n8);
}
__global__ void __launch_bounds__(256) cvt_w4_kernel(
    const float4* w0, const float4* w1, const float4* w2, const float4* w3,
    uint4* o0, uint4* o1, uint4* o2, uint4* o3, int n8)
{
    const float4* in; uint4* out;
    switch (blockIdx.y) {
        case 0:  in = w0; out = o0; break;
        case 1:  in = w1; out = o1; break;
        case 2:  in = w2; out = o2; break;
        default: in = w3; out = o3; break;
    }
    cvt_loop(in, out, n8);
}
__global__ void __launch_bounds__(256) cvt_qv_kernel(
    const float4* a0, const float4* a1, uint4* o0, uint4* o1, int n8)
{
    cvt_loop(blockIdx.y ? a1 : a0, blockIdx.y ? o1 : o0, n8);
}
__global__ void __launch_bounds__(256) cvt_mem_kernel(
    const float* __restrict__ mem, __half* __restrict__ mk,
    __half* __restrict__ mv, int n)
{
    for (int i = blockIdx.x * blockDim.x + threadIdx.x; i < n;
         i += gridDim.x * blockDim.x) {
        float m = mem[i];
        mk[i] = __float2half(m * SQRT_D_C);
        mv[i] = __float2half(m * SQRT_MEM_C);
    }
}

/* =========================================================================
 * proj_h (R10 config): C = groupnorm(celu(A @ W^T + bias)).
 * CTA tile 128x128, BK=64, 8 warps (2x4) of 64x32 warp tiles, 3-stage
 * cp.async, 2 CTAs/SM (16 warps/SM, regs ~124 = RF-filling optimum).
 * grid = (8, rows/128), 256 threads.
 * ========================================================================= */
#define RSTR    144
#define STAGE_B (256 * RSTR)
#define PROJ_SMEM (3 * STAGE_B)          /* 110592 bytes */

__device__ __forceinline__ void proj_issue(
    uint32_t stage, const __half* __restrict__ hA,
    const __half* __restrict__ hW, size_t rowBase, size_t colBase,
    int ch, int tid)
{
#pragma unroll
    for (int i = 0; i < 4; i++) {
        int idx = tid + 256 * i;
        int r = idx >> 3, c = idx & 7;
        cp16(stage + r * RSTR + c * 16,
             hA + (rowBase + r) * 1024 + ch * 64 + c * 8);
        cp16(stage + (128 + r) * RSTR + c * 16,
             hW + (colBase + r) * 1024 + ch * 64 + c * 8);
    }
}

template <typename OT>
__global__ void __launch_bounds__(256, 2) proj_h(
    const __half* __restrict__ hA, const __half* __restrict__ hW,
    const float* __restrict__ bias, const float* __restrict__ gamma,
    const float* __restrict__ beta, OT* __restrict__ C)
{
    extern __shared__ char smem[];
    const uint32_t sb = smem_u32(smem);

    const int tid  = threadIdx.x;
    const int lane = tid & 31;
    const int wid  = tid >> 5;
    const int wm   = wid >> 2;
    const int wn   = wid & 3;
    const int g    = lane >> 2;
    const int tc   = lane & 3;

    const size_t rowBase = (size_t)blockIdx.y * 128;
    const size_t colBase = (size_t)blockIdx.x * 128;

    float acc[4][4][4];
#pragma unroll
    for (int mt = 0; mt < 4; mt++)
#pragma unroll
        for (int nt = 0; nt < 4; nt++)
#pragma unroll
            for (int z = 0; z < 4; z++) acc[mt][nt][z] = 0.f;

    proj_issue(sb + 0 * STAGE_B, hA, hW, rowBase, colBase, 0, tid); CP_COMMIT();
    proj_issue(sb + 1 * STAGE_B, hA, hW, rowBase, colBase, 1, tid); CP_COMMIT();

    const uint32_t aAddrBase =
        (uint32_t)((wm * 64 + (lane & 15)) * RSTR + (lane >> 4) * 16);
    const uint32_t bAddrBase =
        (uint32_t)((128 + wn * 32 + ((lane >> 4) & 1) * 8 + (lane & 7)) * RSTR
                   + ((lane >> 3) & 1) * 16);

    int slot = 0;
    for (int ch = 0; ch < 16; ch++) {
        CP_WAIT(1);
        __syncthreads();
        if (ch + 2 < 16) {
            int ns = slot + 2; if (ns >= 3) ns -= 3;
            proj_issue(sb + ns * STAGE_B, hA, hW, rowBase, colBase, ch + 2, tid);
        }
        CP_COMMIT();

        const uint32_t S = sb + slot * STAGE_B;
        if (++slot == 3) slot = 0;
#pragma unroll
        for (int ks = 0; ks < 4; ks++) {
            uint32_t af[4][4], bf[4][2];
#pragma unroll
            for (int mt = 0; mt < 4; mt++)
                LDSM_X4(af[mt], S + aAddrBase + mt * 16 * RSTR + ks * 32);
#pragma unroll
            for (int j = 0; j < 2; j++) {
                uint32_t t[4];
                LDSM_X4(t, S + bAddrBase + j * 16 * RSTR + ks * 32);
                bf[2 * j][0] = t[0]; bf[2 * j][1] = t[1];
                bf[2 * j + 1][0] = t[2]; bf[2 * j + 1][1] = t[3];
            }
#pragma unroll
            for (int mt = 0; mt < 4; mt++)
#pragma unroll
                for (int nt = 0; nt < 4; nt++)
                    MMA_F16(acc[mt][nt], af[mt], bf[nt]);
        }
    }
    CP_WAIT(0);
    __syncthreads();

    /* ------- epilogue: bias + celu + groupnorm (overlay stage-0 smem) ---- */
    float* SB = (float*)smem;
    float* SG = SB + 128;
    float* SE = SG + 128;
    float* RS = SE + 128;
    float* RQ = RS + 512;

    if (tid < 128) {
        SB[tid] = bias [colBase + tid];
        SG[tid] = gamma[colBase + tid];
        SE[tid] = beta [colBase + tid];
    }
    __syncthreads();

#pragma unroll
    for (int mt = 0; mt < 4; mt++)
#pragma unroll
        for (int half = 0; half < 2; half++) {
            const int r = wm * 64 + mt * 16 + half * 8 + g;
            float s = 0.f, q = 0.f;
#pragma unroll
            for (int nt = 0; nt < 4; nt++) {
                const int c0 = wn * 32 + nt * 8 + 2 * tc;
                float x0 = acc[mt][nt][half * 2 + 0] + SB[c0];
                float x1 = acc[mt][nt][half * 2 + 1] + SB[c0 + 1];
                x0 = (x0 > 0.f) ? x0 : ALPHA_C * expm1f(x0 * (1.0f / ALPHA_C));
                x1 = (x1 > 0.f) ? x1 : ALPHA_C * expm1f(x1 * (1.0f / ALPHA_C));
                acc[mt][nt][half * 2 + 0] = x0;
                acc[mt][nt][half * 2 + 1] = x1;
                s += x0 + x1; q += x0 * x0 + x1 * x1;
            }
            s += __shfl_xor_sync(0xffffffffu, s, 1);
            s += __shfl_xor_sync(0xffffffffu, s, 2);
            q += __shfl_xor_sync(0xffffffffu, q, 1);
            q += __shfl_xor_sync(0xffffffffu, q, 2);
            if (tc == 0) { RS[r * 4 + wn] = s; RQ[r * 4 + wn] = q; }
        }
    __syncthreads();

#pragma unroll
    for (int mt = 0; mt < 4; mt++)
#pragma unroll
        for (int half = 0; half < 2; half++) {
            const int r = wm * 64 + mt * 16 + half * 8 + g;
            const float S = RS[r * 4 + 0] + RS[r * 4 + 1]
                          + RS[r * 4 + 2] + RS[r * 4 + 3];
            const float Q = RQ[r * 4 + 0] + RQ[r * 4 + 1]
                          + RQ[r * 4 + 2] + RQ[r * 4 + 3];
            const float mean = S * (1.f / 128.f);
            const float var  = Q * (1.f / 128.f) - mean * mean;
            const float inv  = rsqrtf(var + EPS_C);
            OT* Crow = C + (rowBase + r) * 1024 + colBase;
#pragma unroll
            for (int nt = 0; nt < 4; nt++) {
                const int c0 = wn * 32 + nt * 8 + 2 * tc;
                float ox = (acc[mt][nt][half * 2 + 0] - mean) * inv * SG[c0]     + SE[c0];
                float oy = (acc[mt][nt][half * 2 + 1] - mean) * inv * SG[c0 + 1] + SE[c0 + 1];
                if constexpr (sizeof(OT) == 4) {
                    *(float2*)&Crow[c0] = make_float2(ox, oy);
                } else {
                    *(__half2*)&Crow[c0] = __floats2half2_rn(ox, oy);
                }
            }
        }
}

/* =========================================================================
 * attn_mma: per (b,h) block; q folded into Wb; fp16 mma.sync scoring.
 * ========================================================================= */
#define ASTR      272
#define KSTAGE_B  (128 * ASTR)
#define ATTN_SMEM (64 * ASTR + 3 * KSTAGE_B + 8 * 64 * 4 + 16)

__device__ __forceinline__ void attn_issue(uint32_t stage, int mbase,
                                           int b, int h, int tid)
{
#pragma unroll
    for (int i = 0; i < 8; i++) {
        int c = tid + 256 * i;
        int r = c >> 4, col = c & 15;
        int mg = mbase + r;
        const __half* src;
        if (mg < Mseq) {
            src = g_hKout + ((size_t)(b * Mseq + mg)) * 1024 + h * 128 + col * 8;
        } else {
            int mm = mg - Mseq;
            if (mm >= MEMN) mm = 0;
            src = g_hMemK + (size_t)mm * 1024 + h * 128 + col * 8;
        }
        cp16(stage + r * ASTR + col * 16, src);
    }
}

__global__ void __launch_bounds__(256, 1) attn_mma(
    const float* __restrict__ mask, const float* __restrict__ Wb,
    const float* __restrict__ bb, const float* __restrict__ Wl,
    const float* __restrict__ bl)
{
    extern __shared__ char sm[];
    const uint32_t sb = smem_u32(sm);
    const uint32_t WQ = sb;
    const uint32_t KT = sb + 64 * ASTR;
    float* PR  = (float*)(sm + 64 * ASTR + 3 * KSTAGE_B);
    float* MSM = PR + 8 * 64;

    const int bh = blockIdx.x, b = bh >> 3, h = bh & 7;
    const int tid = threadIdx.x;
    const int lane = tid & 31;
    const int wid  = tid >> 5;
    const int g    = lane >> 2;
    const int tc   = lane & 3;

    const float* qrow = g_q + (size_t)b * 1024 + h * 128;
    for (int idx = tid; idx < 8192; idx += 256) {
        int o = idx >> 7, d = idx & 127;
        float w = Wb[o * 128 + d] * qrow[d];
        *(__half*)(sm + o * ASTR + d * 2) = __float2half(w);
    }
    if (tid < 32) {
        float s = 0.f;
        for (int m = tid; m < MFULL; m += 32) {
            int mm = (m < Mseq) ? m : (m - Mseq);
            s += mask[b * Mseq + mm];
        }
#pragma unroll
        for (int o = 16; o; o >>= 1) s += __shfl_xor_sync(0xffffffffu, s, o);
        if (tid == 0) MSM[0] = s;
    }

    attn_issue(KT + 0 * KSTAGE_B,   0, b, h, tid); CP_COMMIT();
    attn_issue(KT + 1 * KSTAGE_B, 128, b, h, tid); CP_COMMIT();

    float bbf[8][2], wlf[8][2];
#pragma unroll
    for (int nt = 0; nt < 8; nt++) {
        const int c0 = nt * 8 + 2 * tc;
        bbf[nt][0] = bb[c0]; bbf[nt][1] = bb[c0 + 1];
        wlf[nt][0] = Wl[c0]; wlf[nt][1] = Wl[c0 + 1];
    }
    const float bl0 = bl[0];
    const float* maskb = mask + (size_t)b * Mseq;

    float pool[8][2];
#pragma unroll
    for (int nt = 0; nt < 8; nt++) { pool[nt][0] = 0.f; pool[nt][1] = 0.f; }

    const uint32_t aBase = (uint32_t)((wid * 16 + (lane & 15)) * ASTR + (lane >> 4) * 16);
    const uint32_t bBase = (uint32_t)((((lane >> 4) & 1) * 8 + (lane & 7)) * ASTR
                                      + ((lane >> 3) & 1) * 16);

    for (int it = 0; it < 9; it++) {
        CP_WAIT(1);
        __syncthreads();
        if (it + 2 < 9) {
            attn_issue(KT + ((it + 2) % 3) * KSTAGE_B, (it + 2) * 128, b, h, tid);
            CP_COMMIT();
        }
        const uint32_t S = KT + (it % 3) * KSTAGE_B;

        float acc[8][4];
#pragma unroll
        for (int nt = 0; nt < 8; nt++)
#pragma unroll
            for (int z = 0; z < 4; z++) acc[nt][z] = 0.f;

#pragma unroll
        for (int ks = 0; ks < 8; ks++) {
            uint32_t af[4];
            LDSM_X4(af, S + aBase + ks * 32);
#pragma unroll
            for (int j = 0; j < 4; j++) {
                uint32_t t[4];
                LDSM_X4(t, WQ + bBase + j * 16 * ASTR + ks * 32);
                uint32_t b0[2], b1[2];
                b0[0] = t[0]; b0[1] = t[1];
                b1[0] = t[2]; b1[1] = t[3];
                MMA_F16(acc[2 * j],     af, b0);
                MMA_F16(acc[2 * j + 1], af, b1);
            }
        }

        const int mg0 = it * 128 + wid * 16 + g;
        const int mg1 = mg0 + 8;
        float mv0 = 0.f, mv1 = 0.f;
        if (mg0 < MFULL) mv0 = maskb[(mg0 < Mseq) ? mg0 : (mg0 - Mseq)];
        if (mg1 < MFULL) mv1 = maskb[(mg1 < Mseq) ? mg1 : (mg1 - Mseq)];

        float s0 = 0.f, s1 = 0.f;
#pragma unroll
        for (int nt = 0; nt < 8; nt++) {
            float h00 = fmaxf(acc[nt][0] + bbf[nt][0], 0.f);
            float h01 = fmaxf(acc[nt][1] + bbf[nt][1], 0.f);
            float h10 = fmaxf(acc[nt][2] + bbf[nt][0], 0.f);
            float h11 = fmaxf(acc[nt][3] + bbf[nt][1], 0.f);
            s0 += h00 * wlf[nt][0] + h01 * wlf[nt][1];
            s1 += h10 * wlf[nt][0] + h11 * wlf[nt][1];
            pool[nt][0] += h00 * mv0 + h10 * mv1;
            pool[nt][1] += h01 * mv0 + h11 * mv1;
        }
        s0 += __shfl_xor_sync(0xffffffffu, s0, 1);
        s0 += __shfl_xor_sync(0xffffffffu, s0, 2);
        s1 += __shfl_xor_sync(0xffffffffu, s1, 1);
        s1 += __shfl_xor_sync(0xffffffffu, s1, 2);
        if (tc == 0) {
            if (mg0 < MFULL)
                g_logits[(size_t)bh * MFULL + mg0] = (mv0 == 0.f) ? -1e9f : s0 + bl0;
            if (mg1 < MFULL)
                g_logits[(size_t)bh * MFULL + mg1] = (mv1 == 0.f) ? -1e9f : s1 + bl0;
        }
    }

#pragma unroll
    for (int nt = 0; nt < 8; nt++)
#pragma unroll
        for (int c = 0; c < 2; c++) {
            float v = pool[nt][c];
            v += __shfl_xor_sync(0xffffffffu, v, 4);
            v += __shfl_xor_sync(0xffffffffu, v, 8);
            v += __shfl_xor_sync(0xffffffffu, v, 16);
            if (lane < 4) PR[wid * 64 + nt * 8 + 2 * lane + c] = v;
        }
    __syncthreads();
    if (tid < 64) {
        float s = 0.f;
#pragma unroll
        for (int w = 0; w < 8; w++) s += PR[w * 64 + tid];
        g_pool[(size_t)bh * 64 + tid] = s / MSM[0];
    }
}

/* =========================================================================
 * finalize: softmax(logits), channel gate, weighted sum, output
 * ========================================================================= */
__global__ void __launch_bounds__(256) finalize_kernel(
    const float* __restrict__ Wl2, const float* __restrict__ bl2,
    float* __restrict__ out)
{
    __shared__ float alpha[MFULL];
    __shared__ float red[256];
    __shared__ float pool_s[64];
    __shared__ float vpart[256];

    const int bh = blockIdx.x, b = bh >> 3, h = bh & 7;
    const int tid = threadIdx.x;

    float mx = -INFINITY;
    for (int m = tid; m < MFULL; m += 256) {
        float l = g_logits[(size_t)bh * MFULL + m];
        alpha[m] = l;
        mx = fmaxf(mx, l);
    }
    red[tid] = mx;
    __syncthreads();
    for (int s = 128; s > 0; s >>= 1) {
        if (tid < s) red[tid] = fmaxf(red[tid], red[tid + s]);
        __syncthreads();
    }
    mx = red[0];
    __syncthreads();

    float es = 0.f;
    for (int m = tid; m < MFULL; m += 256) {
        float e = expf(alpha[m] - mx);
        alpha[m] = e;
        es += e;
    }
    red[tid] = es;
    if (tid < 64) pool_s[tid] = g_pool[(size_t)bh * 64 + tid];
    __syncthreads();
    for (int s = 128; s > 0; s >>= 1) {
        if (tid < s) red[tid] += red[tid + s];
        __syncthreads();
    }
    const float sumExp = red[0];

    const int d = tid & 127, half = tid >> 7;
    float acc = 0.f;
    for (int m = half; m < MFULL; m += 2) {
        float a = alpha[m];
        float v;
        if (m < Mseq)
            v = __half2float(g_hV2out[((size_t)(b * Mseq + m)) * 1024 + h * 128 + d]);
        else
            v = __half2float(g_hMemV[(size_t)(m - Mseq) * 1024 + h * 128 + d]);
        acc += a * v;
    }
    vpart[tid] = acc;
    __syncthreads();

    if (tid < 128) {
        float v2p = (vpart[tid] + vpart[tid + 128]) / sumExp;
        float s = bl2[d];
#pragma unroll
        for (int o = 0; o < 64; o++) s += pool_s[o] * Wl2[d * 64 + o];
        float ac = 1.f / (1.f + expf(-s));
        size_t oidx = (size_t)b * Ee + h * Dd + d;
        out[oidx] = g_v1[oidx] * v2p * ac;
    }
}

/* ========================================================================= */
extern "C" void kernel_launch(void* const* d_in, const int* in_sizes, int n_in,
                              void* d_out, int out_size)
{
    const float* query  = (const float*)d_in[0];
    const float* key    = (const float*)d_in[1];
    const float* mask   = (const float*)d_in[2];
    const float* value1 = (const float*)d_in[3];
    const float* value2 = (const float*)d_in[4];
    const float* Wq  = (const float*)d_in[5];  const float* bq  = (const float*)d_in[6];
    const float* gq  = (const float*)d_in[7];  const float* sq  = (const float*)d_in[8];
    const float* Wk  = (const float*)d_in[9];  const float* bk  = (const float*)d_in[10];
    const float* gk  = (const float*)d_in[11]; const float* sk  = (const float*)d_in[12];
    const float* Wv1 = (const float*)d_in[13]; const float* bv1 = (const float*)d_in[14];
    const float* gv1 = (const float*)d_in[15]; const float* sv1 = (const float*)d_in[16];
    const float* Wv2 = (const float*)d_in[17]; const float* bv2 = (const float*)d_in[18];
    const float* gv2 = (const float*)d_in[19]; const float* sv2 = (const float*)d_in[20];
    const float* mem = (const float*)d_in[21];
    const float* Wb  = (const float*)d_in[22]; const float* bb  = (const float*)d_in[23];
    const float* Wl  = (const float*)d_in[24]; const float* bl  = (const float*)d_in[25];
    const float* Wl2 = (const float*)d_in[26]; const float* bl2 = (const float*)d_in[27];
    float* out = (float*)d_out;

    void *pq, *pv1;
    cudaGetSymbolAddress(&pq,  g_q);
    cudaGetSymbolAddress(&pv1, g_v1);
    void *phKey, *phV2in, *phKout, *phV2out, *phQ, *phV1;
    void *phWq, *phWk, *phWv1, *phWv2, *phMemK, *phMemV;
    cudaGetSymbolAddress(&phKey,  g_hKey);
    cudaGetSymbolAddress(&phV2in, g_hV2in);
    cudaGetSymbolAddress(&phKout, g_hKout);
    cudaGetSymbolAddress(&phV2out,g_hV2out);
    cudaGetSymbolAddress(&phQ,    g_hQin);
    cudaGetSymbolAddress(&phV1,   g_hV1in);
    cudaGetSymbolAddress(&phWq,   g_hWq);
    cudaGetSymbolAddress(&phWk,   g_hWk);
    cudaGetSymbolAddress(&phWv1,  g_hWv1);
    cudaGetSymbolAddress(&phWv2,  g_hWv2);
    cudaGetSymbolAddress(&phMemK, g_hMemK);
    cudaGetSymbolAddress(&phMemV, g_hMemV);

    cudaFuncSetAttribute(proj_h<float>,
                         cudaFuncAttributeMaxDynamicSharedMemorySize, PROJ_SMEM);
    cudaFuncSetAttribute(proj_h<__half>,
                         cudaFuncAttributeMaxDynamicSharedMemorySize, PROJ_SMEM);
    cudaFuncSetAttribute(attn_mma,
                         cudaFuncAttributeMaxDynamicSharedMemorySize, ATTN_SMEM);

    static cudaStream_t s1 = nullptr;
    static cudaEvent_t eFork, eW, eK1, eV2, eQ, eV1;
    if (!s1) {
        cudaStreamCreateWithFlags(&s1, cudaStreamNonBlocking);
        cudaEventCreateWithFlags(&eFork, cudaEventDisableTiming);
        cudaEventCreateWithFlags(&eW,    cudaEventDisableTiming);
        cudaEventCreateWithFlags(&eK1,   cudaEventDisableTiming);
        cudaEventCreateWithFlags(&eV2,   cudaEventDisableTiming);
        cudaEventCreateWithFlags(&eQ,    cudaEventDisableTiming);
        cudaEventCreateWithFlags(&eV1,   cudaEventDisableTiming);
    }

    const size_t BIG   = (size_t)Bq * Mseq * Ee;       /* elements        */
    const int    BIGN8 = (int)(BIG / 8);               /* float4 pairs    */
    const int    HALF8 = BIGN8 / 2;
    const size_t HALFE = BIG / 2;                      /* element offset  */

    cudaEventRecord(eFork, 0);
    cudaStreamWaitEvent(s1, eFork, 0);

    /* ---- side stream: weights, key half1, value2, q/v1, mem, small ---- */
    cvt_w4_kernel<<<dim3(512, 4), 256, 0, s1>>>(
        (const float4*)Wq, (const float4*)Wk, (const float4*)Wv1, (const float4*)Wv2,
        (uint4*)phWq, (uint4*)phWk, (uint4*)phWv1, (uint4*)phWv2, Ee * Ee / 8);
    cudaEventRecord(eW, s1);
    cvt_f16_kernel<<<2048, 256, 0, s1>>>(
        (const float4*)key + (HALFE / 4), (uint4*)phKey + HALF8, HALF8);
    cudaEventRecord(eK1, s1);
    cvt_f16_kernel<<<4096, 256, 0, s1>>>((const float4*)value2,
                                         (uint4*)phV2in, BIGN8);
    cudaEventRecord(eV2, s1);
    cvt_qv_kernel<<<dim3(128, 2), 256, 0, s1>>>(
        (const float4*)query, (const float4*)value1,
        (uint4*)phQ, (uint4*)phV1, Bq * Ee / 8);
    cvt_mem_kernel<<<40, 256, 0, s1>>>(mem, (__half*)phMemK, (__half*)phMemV,
                                       MEMN * Ee);
    proj_h<float><<<dim3(8, 1), 256, PROJ_SMEM, s1>>>(
        (const __half*)phQ,  (const __half*)phWq,  bq,  gq,  sq,  (float*)pq);
    cudaEventRecord(eQ, s1);
    proj_h<float><<<dim3(8, 1), 256, PROJ_SMEM, s1>>>(
        (const __half*)phV1, (const __half*)phWv1, bv1, gv1, sv1, (float*)pv1);
    cudaEventRecord(eV1, s1);

    /* ---- main stream: key half0 cvt, projK halves, projV2, attn, fin --- */
    cvt_f16_kernel<<<2048, 256>>>((const float4*)key, (uint4*)phKey, HALF8);
    cudaStreamWaitEvent(0, eW, 0);
    /* projK half0: rows [0, 64K)   — overlaps side cvtK1 + cvtV2 */
    proj_h<__half><<<dim3(8, 512), 256, PROJ_SMEM>>>(
        (const __half*)phKey, (const __half*)phWk, bk, gk, sk, (__half*)phKout);
    cudaStreamWaitEvent(0, eK1, 0);
    /* projK half1: rows [64K, 128K) via offset base pointers */
    proj_h<__half><<<dim3(8, 512), 256, PROJ_SMEM>>>(
        (const __half*)phKey + HALFE, (const __half*)phWk, bk, gk, sk,
        (__half*)phKout + HALFE);
    cudaStreamWaitEvent(0, eV2, 0);
    proj_h<__half><<<dim3(8, 1024), 256, PROJ_SMEM>>>(
        (const __half*)phV2in, (const __half*)phWv2, bv2, gv2, sv2,
        (__half*)phV2out);
    cudaStreamWaitEvent(0, eQ, 0);
    attn_mma<<<Bq * Hh, 256, ATTN_SMEM>>>(mask, Wb, bb, Wl, bl);
    cudaStreamWaitEvent(0, eV1, 0);
    finalize_kernel<<<Bq * Hh, 256>>>(Wl2, bl2, out);
}